// round 15
// baseline (speedup 1.0000x reference)
#include <cuda_runtime.h>
#include <mma.h>
#include <math.h>

using namespace nvcuda;

#define N_NODES   10000
#define N_PADW    10112   // padded for 64-row wmma tiles (158 * 64)
#define N_EDGES   40000
#define N_GRAPHS  250
#define NODES_PG  40
#define NODE_IN   74
#define EDGE_IN   12
#define H         64
#define C_EF      13
#define C_W       14
#define CWH       (C_W * H)   // 896
#define D2        128
#define RD        1024
#define NB        8      // nodes per block (proj / gru)
#define LG        5      // graphs per lstm block
#define OGB       10     // graphs per out block

#define TA_LD     72
#define TB_LD     72

typedef unsigned long long u64;

// ---------------- scratch ---------------------------------------------------
__device__ __align__(16) float g_h0[N_NODES * H];
__device__ __align__(16) float g_h [N_PADW * H];
__device__ float g_deg[N_NODES];
__device__ float g_efeat[N_EDGES * C_EF];
__device__ __align__(16) float g_Wre[H * CWH];               // [i][c*64+o]
__device__ __align__(16) float g_T  [(size_t)N_PADW * CWH];  // [n][c*64+o]
__device__ __align__(16) float g_agg[N_NODES * H];
__device__ __align__(16) float g_feat[N_NODES * D2];
__device__ float g_qstar[N_GRAPHS * 2 * D2];
__device__ float g_hl[N_GRAPHS * D2];
__device__ float g_cl[N_GRAPHS * D2];
// transposed weights [input][output]
__device__ __align__(16) float g_WpT [NODE_IN * H];
__device__ __align__(16) float g_gwT [H * 3 * H];
__device__ __align__(16) float g_ghT [H * 3 * H];
__device__ __align__(16) float g_lwihT[2 * D2 * 4 * D2];     // 256 x 512
__device__ __align__(16) float g_lwhhT[D2 * 4 * D2];         // 128 x 512
__device__ __align__(16) float g_WsT [2 * D2 * RD];          // 256 x 1024

__device__ __forceinline__ float sigf(float x) { return 1.0f / (1.0f + expf(-x)); }

// ---- packed fp32x2 helpers -------------------------------------------------
__device__ __forceinline__ u64 pk2(float a, float b) {
    u64 r; asm("mov.b64 %0, {%1, %2};" : "=l"(r) : "f"(a), "f"(b)); return r;
}
__device__ __forceinline__ void unpk2(u64 v, float& a, float& b) {
    asm("mov.b64 {%0, %1}, %2;" : "=f"(a), "=f"(b) : "l"(v));
}
__device__ __forceinline__ u64 ffma2(u64 a, u64 b, u64 c) {
    u64 d; asm("fma.rn.f32x2 %0, %1, %2, %3;" : "=l"(d) : "l"(a), "l"(b), "l"(c)); return d;
}
__device__ __forceinline__ float to_tf32(float x) {
    float r; asm("cvt.rna.tf32.f32 %0, %1;" : "=f"(r) : "f"(x)); return r;
}

// ---------------- prep: all transposes + Wre + zero deg/agg + h pad ---------
#define S_WPT   (NODE_IN * H)
#define S_GW    (H * 3 * H)
#define S_LWIH  (2 * D2 * 4 * D2)
#define S_LWHH  (D2 * 4 * D2)
#define S_WS    (2 * D2 * RD)
#define S_WRE   (H * CWH)
#define S_HPAD  ((N_PADW - N_NODES) * H)
#define PREP_TOTAL (S_WPT + 2*S_GW + S_LWIH + S_LWHH + S_WS + S_WRE + N_NODES + N_NODES*H + S_HPAD)

__global__ void prep_kernel(const float* __restrict__ Wp,
                            const float* __restrict__ gwih,
                            const float* __restrict__ gwhh,
                            const float* __restrict__ lwih,
                            const float* __restrict__ lwhh,
                            const float* __restrict__ Ws,
                            const float* __restrict__ We,
                            const float* __restrict__ be) {
    int idx = blockIdx.x * blockDim.x + threadIdx.x;
    if (idx < S_WPT) {
        int i = idx / H, o = idx % H;
        g_WpT[idx] = Wp[o * NODE_IN + i]; return;
    }
    idx -= S_WPT;
    if (idx < S_GW) {
        int i = idx / 192, op = idx % 192;
        g_gwT[idx] = gwih[op * H + i]; return;
    }
    idx -= S_GW;
    if (idx < S_GW) {
        int i = idx / 192, op = idx % 192;
        g_ghT[idx] = gwhh[op * H + i]; return;
    }
    idx -= S_GW;
    if (idx < S_LWIH) {
        int i = idx / 512, t = idx % 512;
        g_lwihT[idx] = lwih[t * 256 + i]; return;
    }
    idx -= S_LWIH;
    if (idx < S_LWHH) {
        int i = idx / 512, t = idx % 512;
        g_lwhhT[idx] = lwhh[t * 128 + i]; return;
    }
    idx -= S_LWHH;
    if (idx < S_WS) {
        int i = idx / RD, r = idx % RD;
        g_WsT[idx] = Ws[r * 256 + i]; return;
    }
    idx -= S_WS;
    if (idx < S_WRE) {
        int i = idx / CWH;
        int r = idx % CWH;
        int c = r / H, o = r % H;
        g_Wre[idx] = (c < C_EF) ? We[(i * H + o) * C_EF + c] : be[i * H + o];
        return;
    }
    idx -= S_WRE;
    if (idx < N_NODES) { g_deg[idx] = 0.0f; return; }
    idx -= N_NODES;
    if (idx < N_NODES * H) { g_agg[idx] = 0.0f; return; }
    idx -= N_NODES * H;
    if (idx < S_HPAD) g_h[N_NODES * H + idx] = 0.0f;
}

// ---------------- projection (f32x2) + degree counting ----------------------
#define PROJ_BLKS (N_NODES / NB)              // 1250
#define DEG_BLKS  ((N_EDGES + 127) / 128)     // 313

__global__ __launch_bounds__(128) void projdeg_kernel(const float* __restrict__ na,
                                                      const float* __restrict__ bp,
                                                      const int* __restrict__ dstv) {
    if (blockIdx.x >= PROJ_BLKS) {
        int e = (blockIdx.x - PROJ_BLKS) * 128 + threadIdx.x;
        if (e < N_EDGES) atomicAdd(&g_deg[dstv[e]], 1.0f);
        return;
    }
    int n0 = blockIdx.x * NB;
    int o  = threadIdx.x & 63;
    __shared__ __align__(16) float xs2[NODE_IN][NB];
    for (int idx = threadIdx.x; idx < NB * NODE_IN; idx += 128) {
        int t = idx / NODE_IN, i = idx % NODE_IN;
        xs2[i][t] = na[(n0 + t) * NODE_IN + i];
    }
    __syncthreads();
    if (threadIdx.x >= H) return;
    u64 acc[NB / 2];
    float b = bp[o];
    u64 b2 = pk2(b, b);
#pragma unroll
    for (int j = 0; j < NB / 2; j++) acc[j] = b2;
    for (int i = 0; i < NODE_IN; i++) {
        float w = g_WpT[i * H + o];
        u64 wp = pk2(w, w);
        const ulonglong2* xp = (const ulonglong2*)xs2[i];
#pragma unroll
        for (int j = 0; j < NB / 4; j++) {
            ulonglong2 v = xp[j];
            acc[2 * j]     = ffma2(v.x, wp, acc[2 * j]);
            acc[2 * j + 1] = ffma2(v.y, wp, acc[2 * j + 1]);
        }
    }
#pragma unroll
    for (int j = 0; j < NB / 2; j++) {
        float a, c; unpk2(acc[j], a, c);
        float v0 = fmaxf(a, 0.0f), v1 = fmaxf(c, 0.0f);
        g_h0[(n0 + 2 * j) * H + o] = v0;  g_h[(n0 + 2 * j) * H + o] = v0;
        g_h0[(n0 + 2 * j + 1) * H + o] = v1; g_h[(n0 + 2 * j + 1) * H + o] = v1;
    }
}

// ---------------- gate + efeat ----------------------------------------------
__global__ void gate_kernel(const float* __restrict__ ea,
                            const int* __restrict__ src,
                            const int* __restrict__ dst,
                            const float* __restrict__ Wg,
                            const float* __restrict__ bg) {
    int e = blockIdx.x * 4 + (threadIdx.x >> 5);
    int lane = threadIdx.x & 31;
    if (e >= N_EDGES) return;
    int s = src[e], d = dst[e];
    float acc = g_h0[d * H + lane]      * Wg[lane]
              + g_h0[d * H + 32 + lane] * Wg[32 + lane]
              + g_h0[s * H + lane]      * Wg[64 + lane]
              + g_h0[s * H + 32 + lane] * Wg[96 + lane];
#pragma unroll
    for (int off = 16; off; off >>= 1) acc += __shfl_xor_sync(0xffffffffu, acc, off);
    if (lane < 12) g_efeat[e * C_EF + lane] = ea[e * EDGE_IN + lane];
    if (lane == 12) {
        float t = tanhf(acc + bg[0]);
        g_efeat[e * C_EF + 12] = 0.3f + t * g_deg[d] * g_deg[s];
    }
}

// ---------------- T = h @ Wre via wmma tf32, A-resident channel loop --------
// grid (158, 2), block 128 (4 warps). Block: 64 rows, 7 channel-chunks of 64.
__global__ __launch_bounds__(128) void t_wmma_kernel() {
    __shared__ __align__(16) float As[64][TA_LD];   // 18 KB, tf32 bits
    __shared__ __align__(16) float Bs[64][TB_LD];   // 18 KB, tf32 bits
    int w  = threadIdx.x >> 5;
    int r0 = blockIdx.x * 64;
    int cbase = blockIdx.y * 7;       // channel chunks [cbase, cbase+7)
    // stage A (64 x 64) once, converting to tf32
    for (int idx = threadIdx.x; idx < 64 * 16; idx += 128) {
        int r = idx >> 4, q = idx & 15;
        float4 v = *(const float4*)&g_h[(size_t)(r0 + r) * H + q * 4];
        v.x = to_tf32(v.x); v.y = to_tf32(v.y); v.z = to_tf32(v.z); v.w = to_tf32(v.w);
        *(float4*)&As[r][q * 4] = v;
    }
    __syncthreads();
    // hoist all 8 A-fragments for this warp's 16 rows
    wmma::fragment<wmma::matrix_a, 16, 16, 8, wmma::precision::tf32, wmma::row_major> af[8];
#pragma unroll
    for (int k = 0; k < 8; k++)
        wmma::load_matrix_sync(af[k], &As[w * 16][k * 8], TA_LD);

    wmma::fragment<wmma::matrix_b, 16, 16, 8, wmma::precision::tf32, wmma::row_major> bf;
    for (int cc = 0; cc < 7; cc++) {
        int c0 = (cbase + cc) * 64;
        __syncthreads();   // previous chunk's B reads complete before restage
        for (int idx = threadIdx.x; idx < 64 * 16; idx += 128) {
            int k = idx >> 4, q = idx & 15;
            float4 v = *(const float4*)&g_Wre[(size_t)k * CWH + c0 + q * 4];
            v.x = to_tf32(v.x); v.y = to_tf32(v.y); v.z = to_tf32(v.z); v.w = to_tf32(v.w);
            *(float4*)&Bs[k][q * 4] = v;
        }
        __syncthreads();
        wmma::fragment<wmma::accumulator, 16, 16, 8, float> acc[4];
#pragma unroll
        for (int s = 0; s < 4; s++) wmma::fill_fragment(acc[s], 0.0f);
#pragma unroll
        for (int k = 0; k < 8; k++) {
#pragma unroll
            for (int s = 0; s < 4; s++) {
                wmma::load_matrix_sync(bf, &Bs[k * 8][s * 16], TB_LD);
                wmma::mma_sync(acc[s], af[k], bf, acc[s]);
            }
        }
#pragma unroll
        for (int s = 0; s < 4; s++)
            wmma::store_matrix_sync(g_T + (size_t)(r0 + w * 16) * CWH + c0 + s * 16,
                                    acc[s], CWH, wmma::mem_row_major);
    }
}

// ---------------- edge messages ---------------------------------------------
__global__ void msg_kernel(const int* __restrict__ src,
                           const int* __restrict__ dst) {
    int sub = threadIdx.x >> 6;
    int o   = threadIdx.x & 63;
    int e   = blockIdx.x * 2 + sub;
    __shared__ float ef[2][C_EF];
    if (o < C_EF) ef[sub][o] = g_efeat[e * C_EF + o];
    __syncthreads();
    int s = src[e], d = dst[e];
    const float* Ts = g_T + (size_t)s * CWH;
    float acc = __ldg(&Ts[C_EF * H + o]);
#pragma unroll
    for (int c = 0; c < C_EF; c++) acc = fmaf(ef[sub][c], __ldg(&Ts[c * H + o]), acc);
    atomicAdd(&g_agg[d * H + o], acc);
}

// ---------------- GRU (f32x2, zeroes agg, optional feat write) --------------
__global__ __launch_bounds__(H) void gru_kernel(const float* __restrict__ bih,
                                                const float* __restrict__ bhh,
                                                const float* __restrict__ ncb,
                                                int last) {
    int n0 = blockIdx.x * NB;
    int o  = threadIdx.x;
    __shared__ __align__(16) float xs2[H][NB], hs2[H][NB];
    float nb = ncb[o];
#pragma unroll
    for (int t = 0; t < NB; t++) {
        int a = (n0 + t) * H + o;
        xs2[o][t] = fmaxf(g_agg[a] + nb, 0.0f);
        g_agg[a] = 0.0f;
        hs2[o][t] = g_h[a];
    }
    __syncthreads();
    u64 aR[NB/2], aZ[NB/2], aN[NB/2], cR[NB/2], cZ[NB/2], cN[NB/2];
    u64 z = pk2(0.0f, 0.0f);
#pragma unroll
    for (int j = 0; j < NB/2; j++) { aR[j]=aZ[j]=aN[j]=cR[j]=cZ[j]=cN[j]=z; }
    for (int i = 0; i < H; i++) {
        float wr = g_gwT[i * 192 + o];
        float wz = g_gwT[i * 192 + 64 + o];
        float wn = g_gwT[i * 192 + 128 + o];
        float vr = g_ghT[i * 192 + o];
        float vz = g_ghT[i * 192 + 64 + o];
        float vn = g_ghT[i * 192 + 128 + o];
        u64 wr2 = pk2(wr, wr), wz2 = pk2(wz, wz), wn2 = pk2(wn, wn);
        u64 vr2 = pk2(vr, vr), vz2 = pk2(vz, vz), vn2 = pk2(vn, vn);
        const ulonglong2* xp = (const ulonglong2*)xs2[i];
        const ulonglong2* hp = (const ulonglong2*)hs2[i];
#pragma unroll
        for (int j = 0; j < NB / 4; j++) {
            ulonglong2 xv = xp[j], hv = hp[j];
            aR[2*j]   = ffma2(xv.x, wr2, aR[2*j]);   aR[2*j+1] = ffma2(xv.y, wr2, aR[2*j+1]);
            aZ[2*j]   = ffma2(xv.x, wz2, aZ[2*j]);   aZ[2*j+1] = ffma2(xv.y, wz2, aZ[2*j+1]);
            aN[2*j]   = ffma2(xv.x, wn2, aN[2*j]);   aN[2*j+1] = ffma2(xv.y, wn2, aN[2*j+1]);
            cR[2*j]   = ffma2(hv.x, vr2, cR[2*j]);   cR[2*j+1] = ffma2(hv.y, vr2, cR[2*j+1]);
            cZ[2*j]   = ffma2(hv.x, vz2, cZ[2*j]);   cZ[2*j+1] = ffma2(hv.y, vz2, cZ[2*j+1]);
            cN[2*j]   = ffma2(hv.x, vn2, cN[2*j]);   cN[2*j+1] = ffma2(hv.y, vn2, cN[2*j+1]);
        }
    }
    float biR = bih[o], biZ = bih[H + o], biN = bih[2 * H + o];
    float bhR = bhh[o], bhZ = bhh[H + o], bhN = bhh[2 * H + o];
#pragma unroll
    for (int j = 0; j < NB / 2; j++) {
        float ar0, ar1, az0, az1, an0, an1, cr0, cr1, cz0, cz1, cn0, cn1;
        unpk2(aR[j], ar0, ar1); unpk2(aZ[j], az0, az1); unpk2(aN[j], an0, an1);
        unpk2(cR[j], cr0, cr1); unpk2(cZ[j], cz0, cz1); unpk2(cN[j], cn0, cn1);
#pragma unroll
        for (int k = 0; k < 2; k++) {
            int t = 2 * j + k;
            float ar = k ? ar1 : ar0, az = k ? az1 : az0, an = k ? an1 : an0;
            float cr = k ? cr1 : cr0, cz = k ? cz1 : cz0, cn = k ? cn1 : cn0;
            float r  = sigf(ar + biR + cr + bhR);
            float zz = sigf(az + biZ + cz + bhZ);
            float ng = tanhf(an + biN + r * (cn + bhN));
            float hold = hs2[o][t];
            float hnew = (1.0f - zz) * ng + zz * hold;
            int a = (n0 + t) * H + o;
            g_h[a] = hnew;
            if (last) {
                g_feat[(n0 + t) * D2 + H + o] = hnew;
                g_feat[(n0 + t) * D2 + o]     = g_h0[a];
            }
        }
    }
}

// ---------------- Set2Set LSTM (5 graphs / block, f32x2 over graph pairs) ---
__global__ __launch_bounds__(512) void lstm_kernel(const float* __restrict__ bih,
                                                   const float* __restrict__ bhh) {
    int b0 = blockIdx.x * LG;
    int t  = threadIdx.x;
    __shared__ __align__(16) float qsp[2 * D2][6];
    __shared__ __align__(16) float hsp[D2][6];
    __shared__ float gates[LG][512];
    for (int idx = t; idx < LG * 2 * D2; idx += 512) {
        int g = idx / (2 * D2), i = idx % (2 * D2);
        qsp[i][g] = g_qstar[(b0 + g) * 2 * D2 + i];
    }
    for (int idx = t; idx < LG * D2; idx += 512) {
        int g = idx / D2, i = idx % D2;
        hsp[i][g] = g_hl[(b0 + g) * D2 + i];
    }
    __syncthreads();
    float bv = bih[t] + bhh[t];
    u64 acc2[2]; acc2[0] = pk2(bv, bv); acc2[1] = pk2(bv, bv);
    float acc4 = bv;
#pragma unroll 4
    for (int i = 0; i < 2 * D2; i++) {
        float w = g_lwihT[i * 512 + t];
        u64 wp = pk2(w, w);
        acc2[0] = ffma2(*(const u64*)&qsp[i][0], wp, acc2[0]);
        acc2[1] = ffma2(*(const u64*)&qsp[i][2], wp, acc2[1]);
        acc4 = fmaf(qsp[i][4], w, acc4);
    }
#pragma unroll 4
    for (int i = 0; i < D2; i++) {
        float w = g_lwhhT[i * 512 + t];
        u64 wp = pk2(w, w);
        acc2[0] = ffma2(*(const u64*)&hsp[i][0], wp, acc2[0]);
        acc2[1] = ffma2(*(const u64*)&hsp[i][2], wp, acc2[1]);
        acc4 = fmaf(hsp[i][4], w, acc4);
    }
    float v0, v1; unpk2(acc2[0], v0, v1);
    gates[0][t] = v0; gates[1][t] = v1;
    unpk2(acc2[1], v0, v1);
    gates[2][t] = v0; gates[3][t] = v1;
    gates[4][t] = acc4;
    __syncthreads();
    if (t < D2) {
#pragma unroll
        for (int g = 0; g < LG; g++) {
            float I = sigf(gates[g][t]);
            float F = sigf(gates[g][D2 + t]);
            float G = tanhf(gates[g][2 * D2 + t]);
            float O = sigf(gates[g][3 * D2 + t]);
            int a = (b0 + g) * D2 + t;
            float c = F * g_cl[a] + I * G;
            g_cl[a] = c;
            g_hl[a] = O * tanhf(c);
        }
    }
}

// ---------------- attention + readout (step0: compute hl/cl from biases) ----
__global__ void readout_kernel(int step0,
                               const float* __restrict__ bih,
                               const float* __restrict__ bhh) {
    int b = blockIdx.x;
    int d = threadIdx.x;
    __shared__ float fs[NODES_PG * D2];
    __shared__ float qv[D2];
    __shared__ float sc[NODES_PG];
    __shared__ float ex[NODES_PG];
    if (step0) {
        float I = sigf(bih[d] + bhh[d]);
        float G = tanhf(bih[2 * D2 + d] + bhh[2 * D2 + d]);
        float O = sigf(bih[3 * D2 + d] + bhh[3 * D2 + d]);
        float c = I * G;
        g_cl[b * D2 + d] = c;
        float hv = O * tanhf(c);
        g_hl[b * D2 + d] = hv;
        qv[d] = hv;
    } else {
        qv[d] = g_hl[b * D2 + d];
    }
#pragma unroll
    for (int t = 0; t < NODES_PG; t++)
        fs[t * D2 + d] = g_feat[(size_t)(b * NODES_PG + t) * D2 + d];
    __syncthreads();
    int w = d >> 5, lane = d & 31;
    for (int t = w; t < NODES_PG; t += 4) {
        float a = fs[t * D2 + lane]      * qv[lane]
                + fs[t * D2 + 32 + lane] * qv[32 + lane]
                + fs[t * D2 + 64 + lane] * qv[64 + lane]
                + fs[t * D2 + 96 + lane] * qv[96 + lane];
#pragma unroll
        for (int off = 16; off; off >>= 1) a += __shfl_xor_sync(0xffffffffu, a, off);
        if (lane == 0) sc[t] = a;
    }
    __syncthreads();
    float mx = -1e30f;
#pragma unroll
    for (int t = 0; t < NODES_PG; t++) mx = fmaxf(mx, sc[t]);
    if (d < NODES_PG) ex[d] = expf(sc[d] - mx);
    __syncthreads();
    float den = 0.0f;
#pragma unroll
    for (int t = 0; t < NODES_PG; t++) den += ex[t];
    float acc = 0.0f;
#pragma unroll
    for (int t = 0; t < NODES_PG; t++) acc = fmaf(fs[t * D2 + d], ex[t], acc);
    acc /= den;
    g_qstar[b * 2 * D2 + d]      = qv[d];
    g_qstar[b * 2 * D2 + D2 + d] = acc;
}

// ---------------- output (10 graphs x 256-r tile, f32x2 over graph pairs) ---
__global__ __launch_bounds__(256) void out_kernel(const float* __restrict__ bs,
                                                  const float* __restrict__ prelu_a,
                                                  float* __restrict__ out) {
    int rblk = blockIdx.x & 3;
    int b0   = (blockIdx.x >> 2) * OGB;
    int r    = rblk * 256 + threadIdx.x;
    __shared__ __align__(16) float qsf[2 * D2][OGB];
    for (int idx = threadIdx.x; idx < OGB * 2 * D2; idx += 256) {
        int g = idx / (2 * D2), i = idx % (2 * D2);
        qsf[i][g] = g_qstar[(b0 + g) * 2 * D2 + i];
    }
    __syncthreads();
    float a = prelu_a[0];
    float bv = bs[r];
    u64 acc[OGB / 2];
    u64 b2 = pk2(bv, bv);
#pragma unroll
    for (int p = 0; p < OGB / 2; p++) acc[p] = b2;
#pragma unroll 4
    for (int i = 0; i < 2 * D2; i++) {
        float wv = g_WsT[i * RD + r];
        u64 wp = pk2(wv, wv);
#pragma unroll
        for (int p = 0; p < OGB / 2; p++)
            acc[p] = ffma2(*(const u64*)&qsf[i][2 * p], wp, acc[p]);
    }
#pragma unroll
    for (int p = 0; p < OGB / 2; p++) {
        float v0, v1; unpk2(acc[p], v0, v1);
        out[(size_t)(b0 + 2 * p) * RD + r]     = (v0 >= 0.0f) ? v0 : a * v0;
        out[(size_t)(b0 + 2 * p + 1) * RD + r] = (v1 >= 0.0f) ? v1 : a * v1;
    }
}

// ============================================================================
extern "C" void kernel_launch(void* const* d_in, const int* in_sizes, int n_in,
                              void* d_out, int out_size) {
    const float* node_attr = (const float*)d_in[0];
    const float* edge_attr = (const float*)d_in[1];
    const int*   src       = (const int*)d_in[2];
    const int*   dst       = (const int*)d_in[3];
    const float* Wp   = (const float*)d_in[6];
    const float* bp   = (const float*)d_in[7];
    const float* Wg   = (const float*)d_in[8];
    const float* bg   = (const float*)d_in[9];
    const float* We   = (const float*)d_in[10];
    const float* be   = (const float*)d_in[11];
    const float* ncb  = (const float*)d_in[12];
    const float* gbih = (const float*)d_in[15];
    const float* gbhh = (const float*)d_in[16];
    const float* lbih = (const float*)d_in[19];
    const float* lbhh = (const float*)d_in[20];
    const float* bs   = (const float*)d_in[22];
    const float* pa   = (const float*)d_in[23];
    float* out = (float*)d_out;

    prep_kernel<<<(PREP_TOTAL + 255) / 256, 256>>>(
        Wp, (const float*)d_in[13], (const float*)d_in[14],
        (const float*)d_in[17], (const float*)d_in[18],
        (const float*)d_in[21], We, be);

    projdeg_kernel<<<PROJ_BLKS + DEG_BLKS, 128>>>(node_attr, bp, dst);
    gate_kernel<<<N_EDGES / 4, 128>>>(edge_attr, src, dst, Wg, bg);

    for (int step = 0; step < 3; step++) {
        dim3 tg(N_PADW / 64, 2);
        t_wmma_kernel<<<tg, 128>>>();
        msg_kernel<<<N_EDGES / 2, 128>>>(src, dst);
        gru_kernel<<<N_NODES / NB, H>>>(gbih, gbhh, ncb, step == 2);
    }

    readout_kernel<<<N_GRAPHS, D2>>>(1, lbih, lbhh);
    for (int step = 1; step < 3; step++) {
        lstm_kernel<<<N_GRAPHS / LG, 512>>>(lbih, lbhh);
        readout_kernel<<<N_GRAPHS, D2>>>(0, lbih, lbhh);
    }
    out_kernel<<<(N_GRAPHS / OGB) * 4, 256>>>(bs, pa, out);
}

// round 16
// speedup vs baseline: 1.0619x; 1.0619x over previous
#include <cuda_runtime.h>
#include <mma.h>
#include <math.h>

using namespace nvcuda;

#define N_NODES   10000
#define N_PADW    10112   // padded for 128-row wmma tiles (79 * 128)
#define N_EDGES   40000
#define N_GRAPHS  250
#define NODES_PG  40
#define NODE_IN   74
#define EDGE_IN   12
#define H         64
#define C_EF      13
#define C_W       14
#define CWH       (C_W * H)   // 896
#define D2        128
#define RD        1024
#define NB        8      // nodes per block (proj / gru)
#define LG        5      // graphs per lstm block
#define OGB       10     // graphs per out block

// t_wmma smem layout: A[128][72] + B[64][72]
#define TA_LD     72
#define TB_LD     72
#define T_SMEM_FLOATS (128 * TA_LD + 64 * TB_LD)
#define T_SMEM_BYTES  (T_SMEM_FLOATS * 4)

typedef unsigned long long u64;

// ---------------- scratch ---------------------------------------------------
__device__ __align__(16) float g_h0[N_NODES * H];
__device__ __align__(16) float g_h [N_PADW * H];
__device__ float g_deg[N_NODES];
__device__ float g_efeat[N_EDGES * C_EF];
__device__ __align__(16) float g_Wre[H * CWH];               // [i][c*64+o]
__device__ __align__(16) float g_T  [(size_t)N_PADW * CWH];  // [n][c*64+o]
__device__ __align__(16) float g_agg[N_NODES * H];
__device__ __align__(16) float g_feat[N_NODES * D2];
__device__ float g_qstar[N_GRAPHS * 2 * D2];
__device__ float g_hl[N_GRAPHS * D2];
__device__ float g_cl[N_GRAPHS * D2];
// transposed weights [input][output]
__device__ __align__(16) float g_WpT [NODE_IN * H];
__device__ __align__(16) float g_gwT [H * 3 * H];
__device__ __align__(16) float g_ghT [H * 3 * H];
__device__ __align__(16) float g_lwihT[2 * D2 * 4 * D2];     // 256 x 512
__device__ __align__(16) float g_lwhhT[D2 * 4 * D2];         // 128 x 512
__device__ __align__(16) float g_WsT [2 * D2 * RD];          // 256 x 1024

__device__ __forceinline__ float sigf(float x) { return 1.0f / (1.0f + expf(-x)); }

// ---- packed fp32x2 helpers -------------------------------------------------
__device__ __forceinline__ u64 pk2(float a, float b) {
    u64 r; asm("mov.b64 %0, {%1, %2};" : "=l"(r) : "f"(a), "f"(b)); return r;
}
__device__ __forceinline__ void unpk2(u64 v, float& a, float& b) {
    asm("mov.b64 {%0, %1}, %2;" : "=f"(a), "=f"(b) : "l"(v));
}
__device__ __forceinline__ u64 ffma2(u64 a, u64 b, u64 c) {
    u64 d; asm("fma.rn.f32x2 %0, %1, %2, %3;" : "=l"(d) : "l"(a), "l"(b), "l"(c)); return d;
}
__device__ __forceinline__ float to_tf32(float x) {
    float r; asm("cvt.rna.tf32.f32 %0, %1;" : "=f"(r) : "f"(x)); return r;
}

// ---------------- prep: all transposes + Wre + zero deg/agg + h pad ---------
#define S_WPT   (NODE_IN * H)
#define S_GW    (H * 3 * H)
#define S_LWIH  (2 * D2 * 4 * D2)
#define S_LWHH  (D2 * 4 * D2)
#define S_WS    (2 * D2 * RD)
#define S_WRE   (H * CWH)
#define S_HPAD  ((N_PADW - N_NODES) * H)
#define PREP_TOTAL (S_WPT + 2*S_GW + S_LWIH + S_LWHH + S_WS + S_WRE + N_NODES + N_NODES*H + S_HPAD)

__global__ void prep_kernel(const float* __restrict__ Wp,
                            const float* __restrict__ gwih,
                            const float* __restrict__ gwhh,
                            const float* __restrict__ lwih,
                            const float* __restrict__ lwhh,
                            const float* __restrict__ Ws,
                            const float* __restrict__ We,
                            const float* __restrict__ be) {
    int idx = blockIdx.x * blockDim.x + threadIdx.x;
    if (idx < S_WPT) {
        int i = idx / H, o = idx % H;
        g_WpT[idx] = Wp[o * NODE_IN + i]; return;
    }
    idx -= S_WPT;
    if (idx < S_GW) {
        int i = idx / 192, op = idx % 192;
        g_gwT[idx] = gwih[op * H + i]; return;
    }
    idx -= S_GW;
    if (idx < S_GW) {
        int i = idx / 192, op = idx % 192;
        g_ghT[idx] = gwhh[op * H + i]; return;
    }
    idx -= S_GW;
    if (idx < S_LWIH) {
        int i = idx / 512, t = idx % 512;
        g_lwihT[idx] = lwih[t * 256 + i]; return;
    }
    idx -= S_LWIH;
    if (idx < S_LWHH) {
        int i = idx / 512, t = idx % 512;
        g_lwhhT[idx] = lwhh[t * 128 + i]; return;
    }
    idx -= S_LWHH;
    if (idx < S_WS) {
        int i = idx / RD, r = idx % RD;
        g_WsT[idx] = Ws[r * 256 + i]; return;
    }
    idx -= S_WS;
    if (idx < S_WRE) {
        int i = idx / CWH;
        int r = idx % CWH;
        int c = r / H, o = r % H;
        g_Wre[idx] = (c < C_EF) ? We[(i * H + o) * C_EF + c] : be[i * H + o];
        return;
    }
    idx -= S_WRE;
    if (idx < N_NODES) { g_deg[idx] = 0.0f; return; }
    idx -= N_NODES;
    if (idx < N_NODES * H) { g_agg[idx] = 0.0f; return; }
    idx -= N_NODES * H;
    if (idx < S_HPAD) g_h[N_NODES * H + idx] = 0.0f;
}

// ---------------- projection (f32x2) + degree counting ----------------------
#define PROJ_BLKS (N_NODES / NB)              // 1250
#define DEG_BLKS  ((N_EDGES + 127) / 128)     // 313

__global__ __launch_bounds__(128) void projdeg_kernel(const float* __restrict__ na,
                                                      const float* __restrict__ bp,
                                                      const int* __restrict__ dstv) {
    if (blockIdx.x >= PROJ_BLKS) {
        int e = (blockIdx.x - PROJ_BLKS) * 128 + threadIdx.x;
        if (e < N_EDGES) atomicAdd(&g_deg[dstv[e]], 1.0f);
        return;
    }
    int n0 = blockIdx.x * NB;
    int o  = threadIdx.x & 63;
    __shared__ __align__(16) float xs2[NODE_IN][NB];
    for (int idx = threadIdx.x; idx < NB * NODE_IN; idx += 128) {
        int t = idx / NODE_IN, i = idx % NODE_IN;
        xs2[i][t] = na[(n0 + t) * NODE_IN + i];
    }
    __syncthreads();
    if (threadIdx.x >= H) return;
    u64 acc[NB / 2];
    float b = bp[o];
    u64 b2 = pk2(b, b);
#pragma unroll
    for (int j = 0; j < NB / 2; j++) acc[j] = b2;
    for (int i = 0; i < NODE_IN; i++) {
        float w = g_WpT[i * H + o];
        u64 wp = pk2(w, w);
        const ulonglong2* xp = (const ulonglong2*)xs2[i];
#pragma unroll
        for (int j = 0; j < NB / 4; j++) {
            ulonglong2 v = xp[j];
            acc[2 * j]     = ffma2(v.x, wp, acc[2 * j]);
            acc[2 * j + 1] = ffma2(v.y, wp, acc[2 * j + 1]);
        }
    }
#pragma unroll
    for (int j = 0; j < NB / 2; j++) {
        float a, c; unpk2(acc[j], a, c);
        float v0 = fmaxf(a, 0.0f), v1 = fmaxf(c, 0.0f);
        g_h0[(n0 + 2 * j) * H + o] = v0;  g_h[(n0 + 2 * j) * H + o] = v0;
        g_h0[(n0 + 2 * j + 1) * H + o] = v1; g_h[(n0 + 2 * j + 1) * H + o] = v1;
    }
}

// ---------------- gate + efeat ----------------------------------------------
__global__ void gate_kernel(const float* __restrict__ ea,
                            const int* __restrict__ src,
                            const int* __restrict__ dst,
                            const float* __restrict__ Wg,
                            const float* __restrict__ bg) {
    int e = blockIdx.x * 4 + (threadIdx.x >> 5);
    int lane = threadIdx.x & 31;
    if (e >= N_EDGES) return;
    int s = src[e], d = dst[e];
    float acc = g_h0[d * H + lane]      * Wg[lane]
              + g_h0[d * H + 32 + lane] * Wg[32 + lane]
              + g_h0[s * H + lane]      * Wg[64 + lane]
              + g_h0[s * H + 32 + lane] * Wg[96 + lane];
#pragma unroll
    for (int off = 16; off; off >>= 1) acc += __shfl_xor_sync(0xffffffffu, acc, off);
    if (lane < 12) g_efeat[e * C_EF + lane] = ea[e * EDGE_IN + lane];
    if (lane == 12) {
        float t = tanhf(acc + bg[0]);
        g_efeat[e * C_EF + 12] = 0.3f + t * g_deg[d] * g_deg[s];
    }
}

// ---------------- T = h @ Wre via wmma tf32, converted-at-staging ------------
// grid (79, 14), block 256 (8 warps). Block tile: 128 rows x 64 cols, K=64.
__global__ __launch_bounds__(256) void t_wmma_kernel() {
    extern __shared__ float sm[];
    float* As = sm;                    // [128][72], tf32 bits
    float* Bs = sm + 128 * TA_LD;      // [64][72],  tf32 bits
    int w  = threadIdx.x >> 5;
    int r0 = blockIdx.x * 128;
    int c0 = blockIdx.y * 64;
    for (int idx = threadIdx.x; idx < 128 * 16; idx += 256) {
        int r = idx >> 4, q = idx & 15;
        float4 v = *(const float4*)&g_h[(size_t)(r0 + r) * H + q * 4];
        v.x = to_tf32(v.x); v.y = to_tf32(v.y); v.z = to_tf32(v.z); v.w = to_tf32(v.w);
        *(float4*)&As[r * TA_LD + q * 4] = v;
    }
    for (int idx = threadIdx.x; idx < 64 * 16; idx += 256) {
        int k = idx >> 4, q = idx & 15;
        float4 v = *(const float4*)&g_Wre[(size_t)k * CWH + c0 + q * 4];
        v.x = to_tf32(v.x); v.y = to_tf32(v.y); v.z = to_tf32(v.z); v.w = to_tf32(v.w);
        *(float4*)&Bs[k * TB_LD + q * 4] = v;
    }
    __syncthreads();
    wmma::fragment<wmma::accumulator, 16, 16, 8, float> acc[4];
#pragma unroll
    for (int s = 0; s < 4; s++) wmma::fill_fragment(acc[s], 0.0f);
    wmma::fragment<wmma::matrix_a, 16, 16, 8, wmma::precision::tf32, wmma::row_major> af;
    wmma::fragment<wmma::matrix_b, 16, 16, 8, wmma::precision::tf32, wmma::row_major> bf;
#pragma unroll
    for (int k = 0; k < 8; k++) {
        wmma::load_matrix_sync(af, &As[(w * 16) * TA_LD + k * 8], TA_LD);
#pragma unroll
        for (int s = 0; s < 4; s++) {
            wmma::load_matrix_sync(bf, &Bs[(k * 8) * TB_LD + s * 16], TB_LD);
            wmma::mma_sync(acc[s], af, bf, acc[s]);
        }
    }
#pragma unroll
    for (int s = 0; s < 4; s++)
        wmma::store_matrix_sync(g_T + (size_t)(r0 + w * 16) * CWH + c0 + s * 16,
                                acc[s], CWH, wmma::mem_row_major);
}

// ---------------- edge messages ---------------------------------------------
__global__ void msg_kernel(const int* __restrict__ src,
                           const int* __restrict__ dst) {
    int sub = threadIdx.x >> 6;
    int o   = threadIdx.x & 63;
    int e   = blockIdx.x * 2 + sub;
    __shared__ float ef[2][C_EF];
    if (o < C_EF) ef[sub][o] = g_efeat[e * C_EF + o];
    __syncthreads();
    int s = src[e], d = dst[e];
    const float* Ts = g_T + (size_t)s * CWH;
    float acc = __ldg(&Ts[C_EF * H + o]);
#pragma unroll
    for (int c = 0; c < C_EF; c++) acc = fmaf(ef[sub][c], __ldg(&Ts[c * H + o]), acc);
    atomicAdd(&g_agg[d * H + o], acc);
}

// ---------------- GRU (f32x2, zeroes agg, optional feat write) --------------
__global__ __launch_bounds__(H) void gru_kernel(const float* __restrict__ bih,
                                                const float* __restrict__ bhh,
                                                const float* __restrict__ ncb,
                                                int last) {
    int n0 = blockIdx.x * NB;
    int o  = threadIdx.x;
    __shared__ __align__(16) float xs2[H][NB], hs2[H][NB];
    float nb = ncb[o];
#pragma unroll
    for (int t = 0; t < NB; t++) {
        int a = (n0 + t) * H + o;
        xs2[o][t] = fmaxf(g_agg[a] + nb, 0.0f);
        g_agg[a] = 0.0f;
        hs2[o][t] = g_h[a];
    }
    __syncthreads();
    u64 aR[NB/2], aZ[NB/2], aN[NB/2], cR[NB/2], cZ[NB/2], cN[NB/2];
    u64 z = pk2(0.0f, 0.0f);
#pragma unroll
    for (int j = 0; j < NB/2; j++) { aR[j]=aZ[j]=aN[j]=cR[j]=cZ[j]=cN[j]=z; }
    for (int i = 0; i < H; i++) {
        float wr = g_gwT[i * 192 + o];
        float wz = g_gwT[i * 192 + 64 + o];
        float wn = g_gwT[i * 192 + 128 + o];
        float vr = g_ghT[i * 192 + o];
        float vz = g_ghT[i * 192 + 64 + o];
        float vn = g_ghT[i * 192 + 128 + o];
        u64 wr2 = pk2(wr, wr), wz2 = pk2(wz, wz), wn2 = pk2(wn, wn);
        u64 vr2 = pk2(vr, vr), vz2 = pk2(vz, vz), vn2 = pk2(vn, vn);
        const ulonglong2* xp = (const ulonglong2*)xs2[i];
        const ulonglong2* hp = (const ulonglong2*)hs2[i];
#pragma unroll
        for (int j = 0; j < NB / 4; j++) {
            ulonglong2 xv = xp[j], hv = hp[j];
            aR[2*j]   = ffma2(xv.x, wr2, aR[2*j]);   aR[2*j+1] = ffma2(xv.y, wr2, aR[2*j+1]);
            aZ[2*j]   = ffma2(xv.x, wz2, aZ[2*j]);   aZ[2*j+1] = ffma2(xv.y, wz2, aZ[2*j+1]);
            aN[2*j]   = ffma2(xv.x, wn2, aN[2*j]);   aN[2*j+1] = ffma2(xv.y, wn2, aN[2*j+1]);
            cR[2*j]   = ffma2(hv.x, vr2, cR[2*j]);   cR[2*j+1] = ffma2(hv.y, vr2, cR[2*j+1]);
            cZ[2*j]   = ffma2(hv.x, vz2, cZ[2*j]);   cZ[2*j+1] = ffma2(hv.y, vz2, cZ[2*j+1]);
            cN[2*j]   = ffma2(hv.x, vn2, cN[2*j]);   cN[2*j+1] = ffma2(hv.y, vn2, cN[2*j+1]);
        }
    }
    float biR = bih[o], biZ = bih[H + o], biN = bih[2 * H + o];
    float bhR = bhh[o], bhZ = bhh[H + o], bhN = bhh[2 * H + o];
#pragma unroll
    for (int j = 0; j < NB / 2; j++) {
        float ar0, ar1, az0, az1, an0, an1, cr0, cr1, cz0, cz1, cn0, cn1;
        unpk2(aR[j], ar0, ar1); unpk2(aZ[j], az0, az1); unpk2(aN[j], an0, an1);
        unpk2(cR[j], cr0, cr1); unpk2(cZ[j], cz0, cz1); unpk2(cN[j], cn0, cn1);
#pragma unroll
        for (int k = 0; k < 2; k++) {
            int t = 2 * j + k;
            float ar = k ? ar1 : ar0, az = k ? az1 : az0, an = k ? an1 : an0;
            float cr = k ? cr1 : cr0, cz = k ? cz1 : cz0, cn = k ? cn1 : cn0;
            float r  = sigf(ar + biR + cr + bhR);
            float zz = sigf(az + biZ + cz + bhZ);
            float ng = tanhf(an + biN + r * (cn + bhN));
            float hold = hs2[o][t];
            float hnew = (1.0f - zz) * ng + zz * hold;
            int a = (n0 + t) * H + o;
            g_h[a] = hnew;
            if (last) {
                g_feat[(n0 + t) * D2 + H + o] = hnew;
                g_feat[(n0 + t) * D2 + o]     = g_h0[a];
            }
        }
    }
}

// ---------------- Set2Set LSTM (5 graphs / block, f32x2 over graph pairs) ---
__global__ __launch_bounds__(512) void lstm_kernel(const float* __restrict__ bih,
                                                   const float* __restrict__ bhh) {
    int b0 = blockIdx.x * LG;
    int t  = threadIdx.x;
    __shared__ __align__(16) float qsp[2 * D2][6];
    __shared__ __align__(16) float hsp[D2][6];
    __shared__ float gates[LG][512];
    for (int idx = t; idx < LG * 2 * D2; idx += 512) {
        int g = idx / (2 * D2), i = idx % (2 * D2);
        qsp[i][g] = g_qstar[(b0 + g) * 2 * D2 + i];
    }
    for (int idx = t; idx < LG * D2; idx += 512) {
        int g = idx / D2, i = idx % D2;
        hsp[i][g] = g_hl[(b0 + g) * D2 + i];
    }
    __syncthreads();
    float bv = bih[t] + bhh[t];
    u64 acc2[2]; acc2[0] = pk2(bv, bv); acc2[1] = pk2(bv, bv);
    float acc4 = bv;
#pragma unroll 4
    for (int i = 0; i < 2 * D2; i++) {
        float w = g_lwihT[i * 512 + t];
        u64 wp = pk2(w, w);
        acc2[0] = ffma2(*(const u64*)&qsp[i][0], wp, acc2[0]);
        acc2[1] = ffma2(*(const u64*)&qsp[i][2], wp, acc2[1]);
        acc4 = fmaf(qsp[i][4], w, acc4);
    }
#pragma unroll 4
    for (int i = 0; i < D2; i++) {
        float w = g_lwhhT[i * 512 + t];
        u64 wp = pk2(w, w);
        acc2[0] = ffma2(*(const u64*)&hsp[i][0], wp, acc2[0]);
        acc2[1] = ffma2(*(const u64*)&hsp[i][2], wp, acc2[1]);
        acc4 = fmaf(hsp[i][4], w, acc4);
    }
    float v0, v1; unpk2(acc2[0], v0, v1);
    gates[0][t] = v0; gates[1][t] = v1;
    unpk2(acc2[1], v0, v1);
    gates[2][t] = v0; gates[3][t] = v1;
    gates[4][t] = acc4;
    __syncthreads();
    if (t < D2) {
#pragma unroll
        for (int g = 0; g < LG; g++) {
            float I = sigf(gates[g][t]);
            float F = sigf(gates[g][D2 + t]);
            float G = tanhf(gates[g][2 * D2 + t]);
            float O = sigf(gates[g][3 * D2 + t]);
            int a = (b0 + g) * D2 + t;
            float c = F * g_cl[a] + I * G;
            g_cl[a] = c;
            g_hl[a] = O * tanhf(c);
        }
    }
}

// ---------------- attention + readout (step0: compute hl/cl from biases) ----
__global__ void readout_kernel(int step0,
                               const float* __restrict__ bih,
                               const float* __restrict__ bhh) {
    int b = blockIdx.x;
    int d = threadIdx.x;
    __shared__ float fs[NODES_PG * D2];
    __shared__ float qv[D2];
    __shared__ float sc[NODES_PG];
    __shared__ float ex[NODES_PG];
    if (step0) {
        float I = sigf(bih[d] + bhh[d]);
        float G = tanhf(bih[2 * D2 + d] + bhh[2 * D2 + d]);
        float O = sigf(bih[3 * D2 + d] + bhh[3 * D2 + d]);
        float c = I * G;
        g_cl[b * D2 + d] = c;
        float hv = O * tanhf(c);
        g_hl[b * D2 + d] = hv;
        qv[d] = hv;
    } else {
        qv[d] = g_hl[b * D2 + d];
    }
#pragma unroll
    for (int t = 0; t < NODES_PG; t++)
        fs[t * D2 + d] = g_feat[(size_t)(b * NODES_PG + t) * D2 + d];
    __syncthreads();
    int w = d >> 5, lane = d & 31;
    for (int t = w; t < NODES_PG; t += 4) {
        float a = fs[t * D2 + lane]      * qv[lane]
                + fs[t * D2 + 32 + lane] * qv[32 + lane]
                + fs[t * D2 + 64 + lane] * qv[64 + lane]
                + fs[t * D2 + 96 + lane] * qv[96 + lane];
#pragma unroll
        for (int off = 16; off; off >>= 1) a += __shfl_xor_sync(0xffffffffu, a, off);
        if (lane == 0) sc[t] = a;
    }
    __syncthreads();
    float mx = -1e30f;
#pragma unroll
    for (int t = 0; t < NODES_PG; t++) mx = fmaxf(mx, sc[t]);
    if (d < NODES_PG) ex[d] = expf(sc[d] - mx);
    __syncthreads();
    float den = 0.0f;
#pragma unroll
    for (int t = 0; t < NODES_PG; t++) den += ex[t];
    float acc = 0.0f;
#pragma unroll
    for (int t = 0; t < NODES_PG; t++) acc = fmaf(fs[t * D2 + d], ex[t], acc);
    acc /= den;
    g_qstar[b * 2 * D2 + d]      = qv[d];
    g_qstar[b * 2 * D2 + D2 + d] = acc;
}

// ---------------- output (10 graphs x 256-r tile, f32x2 over graph pairs) ---
__global__ __launch_bounds__(256) void out_kernel(const float* __restrict__ bs,
                                                  const float* __restrict__ prelu_a,
                                                  float* __restrict__ out) {
    int rblk = blockIdx.x & 3;
    int b0   = (blockIdx.x >> 2) * OGB;
    int r    = rblk * 256 + threadIdx.x;
    __shared__ __align__(16) float qsf[2 * D2][OGB];
    for (int idx = threadIdx.x; idx < OGB * 2 * D2; idx += 256) {
        int g = idx / (2 * D2), i = idx % (2 * D2);
        qsf[i][g] = g_qstar[(b0 + g) * 2 * D2 + i];
    }
    __syncthreads();
    float a = prelu_a[0];
    float bv = bs[r];
    u64 acc[OGB / 2];
    u64 b2 = pk2(bv, bv);
#pragma unroll
    for (int p = 0; p < OGB / 2; p++) acc[p] = b2;
#pragma unroll 4
    for (int i = 0; i < 2 * D2; i++) {
        float wv = g_WsT[i * RD + r];
        u64 wp = pk2(wv, wv);
#pragma unroll
        for (int p = 0; p < OGB / 2; p++)
            acc[p] = ffma2(*(const u64*)&qsf[i][2 * p], wp, acc[p]);
    }
#pragma unroll
    for (int p = 0; p < OGB / 2; p++) {
        float v0, v1; unpk2(acc[p], v0, v1);
        out[(size_t)(b0 + 2 * p) * RD + r]     = (v0 >= 0.0f) ? v0 : a * v0;
        out[(size_t)(b0 + 2 * p + 1) * RD + r] = (v1 >= 0.0f) ? v1 : a * v1;
    }
}

// ============================================================================
extern "C" void kernel_launch(void* const* d_in, const int* in_sizes, int n_in,
                              void* d_out, int out_size) {
    const float* node_attr = (const float*)d_in[0];
    const float* edge_attr = (const float*)d_in[1];
    const int*   src       = (const int*)d_in[2];
    const int*   dst       = (const int*)d_in[3];
    const float* Wp   = (const float*)d_in[6];
    const float* bp   = (const float*)d_in[7];
    const float* Wg   = (const float*)d_in[8];
    const float* bg   = (const float*)d_in[9];
    const float* We   = (const float*)d_in[10];
    const float* be   = (const float*)d_in[11];
    const float* ncb  = (const float*)d_in[12];
    const float* gbih = (const float*)d_in[15];
    const float* gbhh = (const float*)d_in[16];
    const float* lbih = (const float*)d_in[19];
    const float* lbhh = (const float*)d_in[20];
    const float* bs   = (const float*)d_in[22];
    const float* pa   = (const float*)d_in[23];
    float* out = (float*)d_out;

    static int attr_set = 0;
    if (!attr_set) {
        cudaFuncSetAttribute(t_wmma_kernel, cudaFuncAttributeMaxDynamicSharedMemorySize,
                             T_SMEM_BYTES);
        attr_set = 1;
    }

    prep_kernel<<<(PREP_TOTAL + 255) / 256, 256>>>(
        Wp, (const float*)d_in[13], (const float*)d_in[14],
        (const float*)d_in[17], (const float*)d_in[18],
        (const float*)d_in[21], We, be);

    projdeg_kernel<<<PROJ_BLKS + DEG_BLKS, 128>>>(node_attr, bp, dst);
    gate_kernel<<<N_EDGES / 4, 128>>>(edge_attr, src, dst, Wg, bg);

    for (int step = 0; step < 3; step++) {
        dim3 tg(N_PADW / 128, CWH / 64);
        t_wmma_kernel<<<tg, 256, T_SMEM_BYTES>>>();
        msg_kernel<<<N_EDGES / 2, 128>>>(src, dst);
        gru_kernel<<<N_NODES / NB, H>>>(gbih, gbhh, ncb, step == 2);
    }

    readout_kernel<<<N_GRAPHS, D2>>>(1, lbih, lbhh);
    for (int step = 1; step < 3; step++) {
        lstm_kernel<<<N_GRAPHS / LG, 512>>>(lbih, lbhh);
        readout_kernel<<<N_GRAPHS, D2>>>(0, lbih, lbhh);
    }
    out_kernel<<<(N_GRAPHS / OGB) * 4, 256>>>(bs, pa, out);
}

// round 17
// speedup vs baseline: 1.2383x; 1.1660x over previous
#include <cuda_runtime.h>
#include <cuda_fp16.h>
#include <mma.h>
#include <math.h>

using namespace nvcuda;

#define N_NODES   10000
#define N_PADW    10112   // padded for 128-row wmma tiles (79 * 128)
#define N_EDGES   40000
#define N_GRAPHS  250
#define NODES_PG  40
#define NODE_IN   74
#define EDGE_IN   12
#define H         64
#define C_EF      13
#define C_W       14
#define CWH       (C_W * H)   // 896
#define D2        128
#define RD        1024
#define NB        8      // nodes per block (proj / gru)
#define LG        5      // graphs per lstm block
#define OGB       10     // graphs per out block

#define TA_LD     72     // halves per row (conflict-free ldmatrix)
#define TB_LD     72

typedef unsigned long long u64;

// ---------------- scratch ---------------------------------------------------
__device__ __align__(16) float  g_h0[N_NODES * H];
__device__ __align__(16) float  g_h [N_NODES * H];
__device__ __align__(16) __half g_hH[N_PADW * H];            // half mirror of h
__device__ float g_deg[N_NODES];
__device__ float g_efeat[N_EDGES * C_EF];
__device__ __align__(16) __half g_WreH[H * CWH];             // [i][c*64+o] half
__device__ __align__(16) float  g_T  [(size_t)N_PADW * CWH]; // [n][c*64+o]
__device__ __align__(16) float  g_agg[N_NODES * H];
__device__ __align__(16) float  g_feat[N_NODES * D2];
__device__ float g_qstar[N_GRAPHS * 2 * D2];
__device__ float g_hl[N_GRAPHS * D2];
__device__ float g_cl[N_GRAPHS * D2];
// transposed weights [input][output]
__device__ __align__(16) float g_WpT [NODE_IN * H];
__device__ __align__(16) float g_gwT [H * 3 * H];
__device__ __align__(16) float g_ghT [H * 3 * H];
__device__ __align__(16) float g_lwihT[2 * D2 * 4 * D2];     // 256 x 512
__device__ __align__(16) float g_lwhhT[D2 * 4 * D2];         // 128 x 512
__device__ __align__(16) float g_WsT [2 * D2 * RD];          // 256 x 1024

__device__ __forceinline__ float sigf(float x) { return 1.0f / (1.0f + expf(-x)); }

// ---- packed fp32x2 helpers -------------------------------------------------
__device__ __forceinline__ u64 pk2(float a, float b) {
    u64 r; asm("mov.b64 %0, {%1, %2};" : "=l"(r) : "f"(a), "f"(b)); return r;
}
__device__ __forceinline__ void unpk2(u64 v, float& a, float& b) {
    asm("mov.b64 {%0, %1}, %2;" : "=f"(a), "=f"(b) : "l"(v));
}
__device__ __forceinline__ u64 ffma2(u64 a, u64 b, u64 c) {
    u64 d; asm("fma.rn.f32x2 %0, %1, %2, %3;" : "=l"(d) : "l"(a), "l"(b), "l"(c)); return d;
}

// ---------------- prep: transposes + WreH + zero deg/agg + h pads -----------
#define S_WPT   (NODE_IN * H)
#define S_GW    (H * 3 * H)
#define S_LWIH  (2 * D2 * 4 * D2)
#define S_LWHH  (D2 * 4 * D2)
#define S_WS    (2 * D2 * RD)
#define S_WRE   (H * CWH)
#define S_HPADH ((N_PADW - N_NODES) * H)
#define PREP_TOTAL (S_WPT + 2*S_GW + S_LWIH + S_LWHH + S_WS + S_WRE + N_NODES + N_NODES*H + S_HPADH)

__global__ void prep_kernel(const float* __restrict__ Wp,
                            const float* __restrict__ gwih,
                            const float* __restrict__ gwhh,
                            const float* __restrict__ lwih,
                            const float* __restrict__ lwhh,
                            const float* __restrict__ Ws,
                            const float* __restrict__ We,
                            const float* __restrict__ be) {
    int idx = blockIdx.x * blockDim.x + threadIdx.x;
    if (idx < S_WPT) {
        int i = idx / H, o = idx % H;
        g_WpT[idx] = Wp[o * NODE_IN + i]; return;
    }
    idx -= S_WPT;
    if (idx < S_GW) {
        int i = idx / 192, op = idx % 192;
        g_gwT[idx] = gwih[op * H + i]; return;
    }
    idx -= S_GW;
    if (idx < S_GW) {
        int i = idx / 192, op = idx % 192;
        g_ghT[idx] = gwhh[op * H + i]; return;
    }
    idx -= S_GW;
    if (idx < S_LWIH) {
        int i = idx / 512, t = idx % 512;
        g_lwihT[idx] = lwih[t * 256 + i]; return;
    }
    idx -= S_LWIH;
    if (idx < S_LWHH) {
        int i = idx / 512, t = idx % 512;
        g_lwhhT[idx] = lwhh[t * 128 + i]; return;
    }
    idx -= S_LWHH;
    if (idx < S_WS) {
        int i = idx / RD, r = idx % RD;
        g_WsT[idx] = Ws[r * 256 + i]; return;
    }
    idx -= S_WS;
    if (idx < S_WRE) {                       // WreH[i][c*64+o] (half)
        int i = idx / CWH;
        int r = idx % CWH;
        int c = r / H, o = r % H;
        float v = (c < C_EF) ? We[(i * H + o) * C_EF + c] : be[i * H + o];
        g_WreH[idx] = __float2half(v);
        return;
    }
    idx -= S_WRE;
    if (idx < N_NODES) { g_deg[idx] = 0.0f; return; }
    idx -= N_NODES;
    if (idx < N_NODES * H) { g_agg[idx] = 0.0f; return; }
    idx -= N_NODES * H;
    if (idx < S_HPADH) g_hH[N_NODES * H + idx] = __float2half(0.0f);
}

// ---------------- projection (f32x2) + degree counting ----------------------
#define PROJ_BLKS (N_NODES / NB)              // 1250
#define DEG_BLKS  ((N_EDGES + 127) / 128)     // 313

__global__ __launch_bounds__(128) void projdeg_kernel(const float* __restrict__ na,
                                                      const float* __restrict__ bp,
                                                      const int* __restrict__ dstv) {
    if (blockIdx.x >= PROJ_BLKS) {
        int e = (blockIdx.x - PROJ_BLKS) * 128 + threadIdx.x;
        if (e < N_EDGES) atomicAdd(&g_deg[dstv[e]], 1.0f);
        return;
    }
    int n0 = blockIdx.x * NB;
    int o  = threadIdx.x & 63;
    __shared__ __align__(16) float xs2[NODE_IN][NB];
    for (int idx = threadIdx.x; idx < NB * NODE_IN; idx += 128) {
        int t = idx / NODE_IN, i = idx % NODE_IN;
        xs2[i][t] = na[(n0 + t) * NODE_IN + i];
    }
    __syncthreads();
    if (threadIdx.x >= H) return;
    u64 acc[NB / 2];
    float b = bp[o];
    u64 b2 = pk2(b, b);
#pragma unroll
    for (int j = 0; j < NB / 2; j++) acc[j] = b2;
    for (int i = 0; i < NODE_IN; i++) {
        float w = g_WpT[i * H + o];
        u64 wp = pk2(w, w);
        const ulonglong2* xp = (const ulonglong2*)xs2[i];
#pragma unroll
        for (int j = 0; j < NB / 4; j++) {
            ulonglong2 v = xp[j];
            acc[2 * j]     = ffma2(v.x, wp, acc[2 * j]);
            acc[2 * j + 1] = ffma2(v.y, wp, acc[2 * j + 1]);
        }
    }
#pragma unroll
    for (int j = 0; j < NB / 2; j++) {
        float a, c; unpk2(acc[j], a, c);
        float v0 = fmaxf(a, 0.0f), v1 = fmaxf(c, 0.0f);
        int a0 = (n0 + 2 * j) * H + o, a1 = (n0 + 2 * j + 1) * H + o;
        g_h0[a0] = v0;  g_h[a0] = v0;  g_hH[a0] = __float2half(v0);
        g_h0[a1] = v1;  g_h[a1] = v1;  g_hH[a1] = __float2half(v1);
    }
}

// ---------------- gate + efeat ----------------------------------------------
__global__ void gate_kernel(const float* __restrict__ ea,
                            const int* __restrict__ src,
                            const int* __restrict__ dst,
                            const float* __restrict__ Wg,
                            const float* __restrict__ bg) {
    int e = blockIdx.x * 4 + (threadIdx.x >> 5);
    int lane = threadIdx.x & 31;
    if (e >= N_EDGES) return;
    int s = src[e], d = dst[e];
    float acc = g_h0[d * H + lane]      * Wg[lane]
              + g_h0[d * H + 32 + lane] * Wg[32 + lane]
              + g_h0[s * H + lane]      * Wg[64 + lane]
              + g_h0[s * H + 32 + lane] * Wg[96 + lane];
#pragma unroll
    for (int off = 16; off; off >>= 1) acc += __shfl_xor_sync(0xffffffffu, acc, off);
    if (lane < 12) g_efeat[e * C_EF + lane] = ea[e * EDGE_IN + lane];
    if (lane == 12) {
        float t = tanhf(acc + bg[0]);
        g_efeat[e * C_EF + 12] = 0.3f + t * g_deg[d] * g_deg[s];
    }
}

// ---------------- T = h @ Wre via wmma fp16 (ldmatrix path) ------------------
// grid (79, 14), block 256 (8 warps). Block tile: 128 rows x 64 cols, K=64.
__global__ __launch_bounds__(256) void t_wmma_kernel() {
    __shared__ __align__(16) __half As[128][TA_LD];   // 18 KB
    __shared__ __align__(16) __half Bs[64][TB_LD];    // 9 KB
    int w  = threadIdx.x >> 5;
    int r0 = blockIdx.x * 128;
    int c0 = blockIdx.y * 64;
    // stage A (128 x 64 halves) via 16B chunks
    for (int idx = threadIdx.x; idx < 128 * 8; idx += 256) {
        int r = idx >> 3, q = idx & 7;
        uint4 v = *(const uint4*)&g_hH[(size_t)(r0 + r) * H + q * 8];
        *(uint4*)&As[r][q * 8] = v;
    }
    // stage B (64 x 64 halves)
    for (int idx = threadIdx.x; idx < 64 * 8; idx += 256) {
        int k = idx >> 3, q = idx & 7;
        uint4 v = *(const uint4*)&g_WreH[(size_t)k * CWH + c0 + q * 8];
        *(uint4*)&Bs[k][q * 8] = v;
    }
    __syncthreads();
    wmma::fragment<wmma::accumulator, 16, 16, 16, float> acc[4];
#pragma unroll
    for (int s = 0; s < 4; s++) wmma::fill_fragment(acc[s], 0.0f);
    wmma::fragment<wmma::matrix_a, 16, 16, 16, __half, wmma::row_major> af;
    wmma::fragment<wmma::matrix_b, 16, 16, 16, __half, wmma::row_major> bf;
#pragma unroll
    for (int k = 0; k < 4; k++) {
        wmma::load_matrix_sync(af, &As[w * 16][k * 16], TA_LD);
#pragma unroll
        for (int s = 0; s < 4; s++) {
            wmma::load_matrix_sync(bf, &Bs[k * 16][s * 16], TB_LD);
            wmma::mma_sync(acc[s], af, bf, acc[s]);
        }
    }
#pragma unroll
    for (int s = 0; s < 4; s++)
        wmma::store_matrix_sync(g_T + (size_t)(r0 + w * 16) * CWH + c0 + s * 16,
                                acc[s], CWH, wmma::mem_row_major);
}

// ---------------- edge messages ---------------------------------------------
__global__ void msg_kernel(const int* __restrict__ src,
                           const int* __restrict__ dst) {
    int sub = threadIdx.x >> 6;
    int o   = threadIdx.x & 63;
    int e   = blockIdx.x * 2 + sub;
    __shared__ float ef[2][C_EF];
    if (o < C_EF) ef[sub][o] = g_efeat[e * C_EF + o];
    __syncthreads();
    int s = src[e], d = dst[e];
    const float* Ts = g_T + (size_t)s * CWH;
    float acc = __ldg(&Ts[C_EF * H + o]);
#pragma unroll
    for (int c = 0; c < C_EF; c++) acc = fmaf(ef[sub][c], __ldg(&Ts[c * H + o]), acc);
    atomicAdd(&g_agg[d * H + o], acc);
}

// ---------------- GRU (f32x2, zeroes agg, optional feat write) --------------
__global__ __launch_bounds__(H) void gru_kernel(const float* __restrict__ bih,
                                                const float* __restrict__ bhh,
                                                const float* __restrict__ ncb,
                                                int last) {
    int n0 = blockIdx.x * NB;
    int o  = threadIdx.x;
    __shared__ __align__(16) float xs2[H][NB], hs2[H][NB];
    float nb = ncb[o];
#pragma unroll
    for (int t = 0; t < NB; t++) {
        int a = (n0 + t) * H + o;
        xs2[o][t] = fmaxf(g_agg[a] + nb, 0.0f);
        g_agg[a] = 0.0f;
        hs2[o][t] = g_h[a];
    }
    __syncthreads();
    u64 aR[NB/2], aZ[NB/2], aN[NB/2], cR[NB/2], cZ[NB/2], cN[NB/2];
    u64 z = pk2(0.0f, 0.0f);
#pragma unroll
    for (int j = 0; j < NB/2; j++) { aR[j]=aZ[j]=aN[j]=cR[j]=cZ[j]=cN[j]=z; }
    for (int i = 0; i < H; i++) {
        float wr = g_gwT[i * 192 + o];
        float wz = g_gwT[i * 192 + 64 + o];
        float wn = g_gwT[i * 192 + 128 + o];
        float vr = g_ghT[i * 192 + o];
        float vz = g_ghT[i * 192 + 64 + o];
        float vn = g_ghT[i * 192 + 128 + o];
        u64 wr2 = pk2(wr, wr), wz2 = pk2(wz, wz), wn2 = pk2(wn, wn);
        u64 vr2 = pk2(vr, vr), vz2 = pk2(vz, vz), vn2 = pk2(vn, vn);
        const ulonglong2* xp = (const ulonglong2*)xs2[i];
        const ulonglong2* hp = (const ulonglong2*)hs2[i];
#pragma unroll
        for (int j = 0; j < NB / 4; j++) {
            ulonglong2 xv = xp[j], hv = hp[j];
            aR[2*j]   = ffma2(xv.x, wr2, aR[2*j]);   aR[2*j+1] = ffma2(xv.y, wr2, aR[2*j+1]);
            aZ[2*j]   = ffma2(xv.x, wz2, aZ[2*j]);   aZ[2*j+1] = ffma2(xv.y, wz2, aZ[2*j+1]);
            aN[2*j]   = ffma2(xv.x, wn2, aN[2*j]);   aN[2*j+1] = ffma2(xv.y, wn2, aN[2*j+1]);
            cR[2*j]   = ffma2(hv.x, vr2, cR[2*j]);   cR[2*j+1] = ffma2(hv.y, vr2, cR[2*j+1]);
            cZ[2*j]   = ffma2(hv.x, vz2, cZ[2*j]);   cZ[2*j+1] = ffma2(hv.y, vz2, cZ[2*j+1]);
            cN[2*j]   = ffma2(hv.x, vn2, cN[2*j]);   cN[2*j+1] = ffma2(hv.y, vn2, cN[2*j+1]);
        }
    }
    float biR = bih[o], biZ = bih[H + o], biN = bih[2 * H + o];
    float bhR = bhh[o], bhZ = bhh[H + o], bhN = bhh[2 * H + o];
#pragma unroll
    for (int j = 0; j < NB / 2; j++) {
        float ar0, ar1, az0, az1, an0, an1, cr0, cr1, cz0, cz1, cn0, cn1;
        unpk2(aR[j], ar0, ar1); unpk2(aZ[j], az0, az1); unpk2(aN[j], an0, an1);
        unpk2(cR[j], cr0, cr1); unpk2(cZ[j], cz0, cz1); unpk2(cN[j], cn0, cn1);
#pragma unroll
        for (int k = 0; k < 2; k++) {
            int t = 2 * j + k;
            float ar = k ? ar1 : ar0, az = k ? az1 : az0, an = k ? an1 : an0;
            float cr = k ? cr1 : cr0, cz = k ? cz1 : cz0, cn = k ? cn1 : cn0;
            float r  = sigf(ar + biR + cr + bhR);
            float zz = sigf(az + biZ + cz + bhZ);
            float ng = tanhf(an + biN + r * (cn + bhN));
            float hold = hs2[o][t];
            float hnew = (1.0f - zz) * ng + zz * hold;
            int a = (n0 + t) * H + o;
            g_h[a] = hnew;
            if (last) {
                g_feat[(n0 + t) * D2 + H + o] = hnew;
                g_feat[(n0 + t) * D2 + o]     = g_h0[a];
            } else {
                g_hH[a] = __float2half(hnew);
            }
        }
    }
}

// ---------------- Set2Set LSTM (5 graphs / block, f32x2 over graph pairs) ---
__global__ __launch_bounds__(512) void lstm_kernel(const float* __restrict__ bih,
                                                   const float* __restrict__ bhh) {
    int b0 = blockIdx.x * LG;
    int t  = threadIdx.x;
    __shared__ __align__(16) float qsp[2 * D2][6];
    __shared__ __align__(16) float hsp[D2][6];
    __shared__ float gates[LG][512];
    for (int idx = t; idx < LG * 2 * D2; idx += 512) {
        int g = idx / (2 * D2), i = idx % (2 * D2);
        qsp[i][g] = g_qstar[(b0 + g) * 2 * D2 + i];
    }
    for (int idx = t; idx < LG * D2; idx += 512) {
        int g = idx / D2, i = idx % D2;
        hsp[i][g] = g_hl[(b0 + g) * D2 + i];
    }
    __syncthreads();
    float bv = bih[t] + bhh[t];
    u64 acc2[2]; acc2[0] = pk2(bv, bv); acc2[1] = pk2(bv, bv);
    float acc4 = bv;
#pragma unroll 4
    for (int i = 0; i < 2 * D2; i++) {
        float w = g_lwihT[i * 512 + t];
        u64 wp = pk2(w, w);
        acc2[0] = ffma2(*(const u64*)&qsp[i][0], wp, acc2[0]);
        acc2[1] = ffma2(*(const u64*)&qsp[i][2], wp, acc2[1]);
        acc4 = fmaf(qsp[i][4], w, acc4);
    }
#pragma unroll 4
    for (int i = 0; i < D2; i++) {
        float w = g_lwhhT[i * 512 + t];
        u64 wp = pk2(w, w);
        acc2[0] = ffma2(*(const u64*)&hsp[i][0], wp, acc2[0]);
        acc2[1] = ffma2(*(const u64*)&hsp[i][2], wp, acc2[1]);
        acc4 = fmaf(hsp[i][4], w, acc4);
    }
    float v0, v1; unpk2(acc2[0], v0, v1);
    gates[0][t] = v0; gates[1][t] = v1;
    unpk2(acc2[1], v0, v1);
    gates[2][t] = v0; gates[3][t] = v1;
    gates[4][t] = acc4;
    __syncthreads();
    if (t < D2) {
#pragma unroll
        for (int g = 0; g < LG; g++) {
            float I = sigf(gates[g][t]);
            float F = sigf(gates[g][D2 + t]);
            float G = tanhf(gates[g][2 * D2 + t]);
            float O = sigf(gates[g][3 * D2 + t]);
            int a = (b0 + g) * D2 + t;
            float c = F * g_cl[a] + I * G;
            g_cl[a] = c;
            g_hl[a] = O * tanhf(c);
        }
    }
}

// ---------------- attention + readout (step0: compute hl/cl from biases) ----
__global__ void readout_kernel(int step0,
                               const float* __restrict__ bih,
                               const float* __restrict__ bhh) {
    int b = blockIdx.x;
    int d = threadIdx.x;
    __shared__ float fs[NODES_PG * D2];
    __shared__ float qv[D2];
    __shared__ float sc[NODES_PG];
    __shared__ float ex[NODES_PG];
    if (step0) {
        float I = sigf(bih[d] + bhh[d]);
        float G = tanhf(bih[2 * D2 + d] + bhh[2 * D2 + d]);
        float O = sigf(bih[3 * D2 + d] + bhh[3 * D2 + d]);
        float c = I * G;
        g_cl[b * D2 + d] = c;
        float hv = O * tanhf(c);
        g_hl[b * D2 + d] = hv;
        qv[d] = hv;
    } else {
        qv[d] = g_hl[b * D2 + d];
    }
#pragma unroll
    for (int t = 0; t < NODES_PG; t++)
        fs[t * D2 + d] = g_feat[(size_t)(b * NODES_PG + t) * D2 + d];
    __syncthreads();
    int w = d >> 5, lane = d & 31;
    for (int t = w; t < NODES_PG; t += 4) {
        float a = fs[t * D2 + lane]      * qv[lane]
                + fs[t * D2 + 32 + lane] * qv[32 + lane]
                + fs[t * D2 + 64 + lane] * qv[64 + lane]
                + fs[t * D2 + 96 + lane] * qv[96 + lane];
#pragma unroll
        for (int off = 16; off; off >>= 1) a += __shfl_xor_sync(0xffffffffu, a, off);
        if (lane == 0) sc[t] = a;
    }
    __syncthreads();
    float mx = -1e30f;
#pragma unroll
    for (int t = 0; t < NODES_PG; t++) mx = fmaxf(mx, sc[t]);
    if (d < NODES_PG) ex[d] = expf(sc[d] - mx);
    __syncthreads();
    float den = 0.0f;
#pragma unroll
    for (int t = 0; t < NODES_PG; t++) den += ex[t];
    float acc = 0.0f;
#pragma unroll
    for (int t = 0; t < NODES_PG; t++) acc = fmaf(fs[t * D2 + d], ex[t], acc);
    acc /= den;
    g_qstar[b * 2 * D2 + d]      = qv[d];
    g_qstar[b * 2 * D2 + D2 + d] = acc;
}

// ---------------- output (10 graphs x 256-r tile, f32x2 over graph pairs) ---
__global__ __launch_bounds__(256) void out_kernel(const float* __restrict__ bs,
                                                  const float* __restrict__ prelu_a,
                                                  float* __restrict__ out) {
    int rblk = blockIdx.x & 3;
    int b0   = (blockIdx.x >> 2) * OGB;
    int r    = rblk * 256 + threadIdx.x;
    __shared__ __align__(16) float qsf[2 * D2][OGB];
    for (int idx = threadIdx.x; idx < OGB * 2 * D2; idx += 256) {
        int g = idx / (2 * D2), i = idx % (2 * D2);
        qsf[i][g] = g_qstar[(b0 + g) * 2 * D2 + i];
    }
    __syncthreads();
    float a = prelu_a[0];
    float bv = bs[r];
    u64 acc[OGB / 2];
    u64 b2 = pk2(bv, bv);
#pragma unroll
    for (int p = 0; p < OGB / 2; p++) acc[p] = b2;
#pragma unroll 4
    for (int i = 0; i < 2 * D2; i++) {
        float wv = g_WsT[i * RD + r];
        u64 wp = pk2(wv, wv);
#pragma unroll
        for (int p = 0; p < OGB / 2; p++)
            acc[p] = ffma2(*(const u64*)&qsf[i][2 * p], wp, acc[p]);
    }
#pragma unroll
    for (int p = 0; p < OGB / 2; p++) {
        float v0, v1; unpk2(acc[p], v0, v1);
        out[(size_t)(b0 + 2 * p) * RD + r]     = (v0 >= 0.0f) ? v0 : a * v0;
        out[(size_t)(b0 + 2 * p + 1) * RD + r] = (v1 >= 0.0f) ? v1 : a * v1;
    }
}

// ============================================================================
extern "C" void kernel_launch(void* const* d_in, const int* in_sizes, int n_in,
                              void* d_out, int out_size) {
    const float* node_attr = (const float*)d_in[0];
    const float* edge_attr = (const float*)d_in[1];
    const int*   src       = (const int*)d_in[2];
    const int*   dst       = (const int*)d_in[3];
    const float* Wp   = (const float*)d_in[6];
    const float* bp   = (const float*)d_in[7];
    const float* Wg   = (const float*)d_in[8];
    const float* bg   = (const float*)d_in[9];
    const float* We   = (const float*)d_in[10];
    const float* be   = (const float*)d_in[11];
    const float* ncb  = (const float*)d_in[12];
    const float* gbih = (const float*)d_in[15];
    const float* gbhh = (const float*)d_in[16];
    const float* lbih = (const float*)d_in[19];
    const float* lbhh = (const float*)d_in[20];
    const float* bs   = (const float*)d_in[22];
    const float* pa   = (const float*)d_in[23];
    float* out = (float*)d_out;

    prep_kernel<<<(PREP_TOTAL + 255) / 256, 256>>>(
        Wp, (const float*)d_in[13], (const float*)d_in[14],
        (const float*)d_in[17], (const float*)d_in[18],
        (const float*)d_in[21], We, be);

    projdeg_kernel<<<PROJ_BLKS + DEG_BLKS, 128>>>(node_attr, bp, dst);
    gate_kernel<<<N_EDGES / 4, 128>>>(edge_attr, src, dst, Wg, bg);

    for (int step = 0; step < 3; step++) {
        dim3 tg(N_PADW / 128, CWH / 64);
        t_wmma_kernel<<<tg, 256>>>();
        msg_kernel<<<N_EDGES / 2, 128>>>(src, dst);
        gru_kernel<<<N_NODES / NB, H>>>(gbih, gbhh, ncb, step == 2);
    }

    readout_kernel<<<N_GRAPHS, D2>>>(1, lbih, lbhh);
    for (int step = 1; step < 3; step++) {
        lstm_kernel<<<N_GRAPHS / LG, 512>>>(lbih, lbhh);
        readout_kernel<<<N_GRAPHS, D2>>>(0, lbih, lbhh);
    }
    out_kernel<<<(N_GRAPHS / OGB) * 4, 256>>>(bs, pa, out);
}